// round 10
// baseline (speedup 1.0000x reference)
#include <cuda_runtime.h>
#include <cstdint>
#include <float.h>

#define N_NODES 50000
#define E_RAW   800000
#define E_TOT   850000   // E_RAW + N_NODES self loops
#define H1      15
#define F1      120      // H1*8
#define DIN     128
#define F2      32

#define FULL 0xFFFFFFFFu
#define NSCAN_BLK 98     // ceil(N_NODES / 512)

typedef unsigned long long u64;

// packed f32x2 FMA: acc = a * b + acc (elementwise on two packed floats)
#define FMA2(acc, a, b) \
    asm("fma.rn.f32x2 %0, %1, %2, %0;" : "+l"(acc) : "l"(a), "l"(b))

__device__ __forceinline__ float sum2(u64 p) {
    float lo, hi;
    asm("mov.b64 {%0, %1}, %2;" : "=f"(lo), "=f"(hi) : "l"(p));
    return lo + hi;
}

// ---------------- scratch (device globals; no allocation allowed) ----------------
__device__ int      g_src[(size_t)E_TOT];
__device__ int      g_dst[(size_t)E_TOT];
__device__ int      g_cnt[(size_t)N_NODES];
__device__ int      g_cursor[(size_t)N_NODES];
__device__ int      g_rowstart[(size_t)N_NODES + 1];
__device__ int      g_csr_src[(size_t)E_TOT];
__device__ int      g_part[128];
__device__ int      g_partoff[128];
__device__ unsigned g_is64;                            // edge dtype flag
__device__ u64      g_W1p[2][32][2][120];              // [mat][kq][pair][col] packed W1 rows
__device__ u64      g_W2p[2][30][2][32];               // [mat][kq][pair][col] packed W2 rows
__device__ float    g_xl1[(size_t)N_NODES * F1];
__device__ float    g_xr1[(size_t)N_NODES * F1];
__device__ float    g_h[(size_t)N_NODES * F1];         // layer-1 activations (post ELU)
__device__ float    g_hl2[(size_t)N_NODES * F2];
__device__ float    g_hr2[(size_t)N_NODES * F2];

__device__ __forceinline__ float lrelu(float v) { return v > 0.f ? v : 0.2f * v; }

// ---------------- edge dtype detection (sampled; 1 block) ----------------
__global__ void k_detect(const int* __restrict__ ei_raw) {
    unsigned acc = 0;
    for (int i = threadIdx.x; i < 4096; i += 256)
        acc |= (unsigned)ei_raw[2 * i + 1];
#pragma unroll
    for (int o = 16; o; o >>= 1) acc |= __shfl_xor_sync(FULL, acc, o);
    if ((threadIdx.x & 31) == 0 && acc) atomicOr(&g_is64, 1u);
}

// ---------------- init ----------------
__global__ void k_init() {
    int i = blockIdx.x * blockDim.x + threadIdx.x;
    if (i == 0) g_is64 = 0u;
    if (i < N_NODES) { g_cnt[i] = 0; g_cursor[i] = 0; }
}

// ---------------- pack W matrices into f32x2 row-pairs ----------------
__global__ void k_packW(const float* __restrict__ W1l, const float* __restrict__ W1r,
                        const float* __restrict__ W2l, const float* __restrict__ W2r) {
    int i = blockIdx.x * blockDim.x + threadIdx.x;
    if (i < 2 * 32 * 2 * 120) {
        int mat = i / 7680, rem = i % 7680;
        int kq = rem / 240, rem2 = rem % 240;
        int p = rem2 / 120, col = rem2 % 120;
        const float* W = mat ? W1r : W1l;
        int row = kq * 4 + p * 2;
        u64 lo = __float_as_uint(W[(size_t)row * F1 + col]);
        u64 hi = __float_as_uint(W[(size_t)(row + 1) * F1 + col]);
        g_W1p[mat][kq][p][col] = (hi << 32) | lo;
    }
    if (i < 2 * 30 * 2 * 32) {
        int mat = i / 1920, rem = i % 1920;
        int kq = rem / 64, rem2 = rem % 64;
        int p = rem2 / 32, col = rem2 % 32;
        const float* W = mat ? W2r : W2l;
        int row = kq * 4 + p * 2;
        u64 lo = __float_as_uint(W[(size_t)row * F2 + col]);
        u64 hi = __float_as_uint(W[(size_t)(row + 1) * F2 + col]);
        g_W2p[mat][kq][p][col] = (hi << 32) | lo;
    }
}

// ---------------- normalize edges to int32 + self loops + degree count ----------------
__global__ void k_convert_count(const int* __restrict__ ei_raw) {
    int e = blockIdx.x * blockDim.x + threadIdx.x;
    if (e >= E_TOT) return;
    int src, dst;
    if (e >= E_RAW) {
        src = dst = e - E_RAW;
    } else if (g_is64) {           // flag set -> data is int32
        src = ei_raw[e];
        dst = ei_raw[E_RAW + e];
    } else {                       // int64 data: low word at 2*index
        src = ei_raw[2 * e];
        dst = ei_raw[2 * (E_RAW + e)];
    }
    g_src[e] = src;
    g_dst[e] = dst;
    atomicAdd(&g_cnt[dst], 1);
}

// ---------------- parallel scan: pass A (block partial sums) ----------------
__global__ void k_scan_a() {
    int idx = blockIdx.x * 512 + threadIdx.x;
    int v = (idx < N_NODES) ? g_cnt[idx] : 0;
#pragma unroll
    for (int o = 16; o; o >>= 1) v += __shfl_down_sync(FULL, v, o);
    __shared__ int ws[16];
    if ((threadIdx.x & 31) == 0) ws[threadIdx.x >> 5] = v;
    __syncthreads();
    if (threadIdx.x < 16) {
        int s = ws[threadIdx.x];
#pragma unroll
        for (int o = 8; o; o >>= 1) s += __shfl_down_sync(0xFFFFu, s, o);
        if (threadIdx.x == 0) g_part[blockIdx.x] = s;
    }
}

// ---------------- parallel scan: pass B (scan 98 partials; 1 block x 128) ----------------
__global__ void k_scan_b() {
    int t = threadIdx.x;                       // 128 threads
    int v = (t < NSCAN_BLK) ? g_part[t] : 0;
    int lane = t & 31, wid = t >> 5;
    int inc = v;
#pragma unroll
    for (int o = 1; o < 32; o <<= 1) {
        int u = __shfl_up_sync(FULL, inc, o);
        if (lane >= o) inc += u;
    }
    __shared__ int ws[4];
    if (lane == 31) ws[wid] = inc;
    __syncthreads();
    int woff = 0;
    for (int i = 0; i < wid; i++) woff += ws[i];
    g_partoff[t] = inc - v + woff;             // exclusive
    if (t == 0) g_rowstart[N_NODES] = E_TOT;
}

// ---------------- parallel scan: pass C (block exclusive scan + offset) ----------------
__global__ void k_scan_c() {
    int idx = blockIdx.x * 512 + threadIdx.x;
    int v = (idx < N_NODES) ? g_cnt[idx] : 0;
    int lane = threadIdx.x & 31, wid = threadIdx.x >> 5;
    int inc = v;
#pragma unroll
    for (int o = 1; o < 32; o <<= 1) {
        int u = __shfl_up_sync(FULL, inc, o);
        if (lane >= o) inc += u;
    }
    __shared__ int ws[16];
    if (lane == 31) ws[wid] = inc;
    __syncthreads();
    if (threadIdx.x < 16) {
        int s = ws[threadIdx.x];
#pragma unroll
        for (int o = 1; o < 16; o <<= 1) {
            int u = __shfl_up_sync(0xFFFFu, s, o);
            if (threadIdx.x >= o) s += u;
        }
        ws[threadIdx.x] = s;
    }
    __syncthreads();
    int woff = wid ? ws[wid - 1] : 0;
    if (idx < N_NODES)
        g_rowstart[idx] = inc - v + woff + g_partoff[blockIdx.x];
}

// ---------------- fill CSR (src ids grouped by dst) ----------------
__global__ void k_fill() {
    int e = blockIdx.x * blockDim.x + threadIdx.x;
    if (e >= E_TOT) return;
    int dst = g_dst[e];
    int pos = g_rowstart[dst] + atomicAdd(&g_cursor[dst], 1);
    g_csr_src[pos] = g_src[e];
}

// ---------------- GEMM1: f32x2 packed FMA, smem x-tile, warp = 8 nodes x ONE matrix ----------------
__global__ void k_gemm1(const float* __restrict__ x) {
    __shared__ ulonglong2 sx[32 * 32];          // 32 nodes x 128 floats = 16KB
    int tid = threadIdx.x;
    int nb0 = blockIdx.x * 32;

    const ulonglong2* x4 = (const ulonglong2*)x + (size_t)nb0 * 32;
    for (int i = tid; i < 32 * 32; i += 256)
        if (nb0 + (i >> 5) < N_NODES) sx[i] = x4[i];
    __syncthreads();

    int w = tid >> 5, lane = tid & 31;
    int mat = w & 1;
    int l0 = (w >> 1) * 8;
    int nb = nb0 + l0;
    if (nb >= N_NODES) return;                  // N % 8 == 0 -> whole group valid

    float* outp = mat ? g_xr1 : g_xl1;
    int g = lane < 30 ? lane : 0;               // lanes 30,31 compute garbage, never store

    u64 pacc[8][4];
#pragma unroll
    for (int j = 0; j < 8; j++)
#pragma unroll
        for (int c = 0; c < 4; c++) pacc[j][c] = 0ULL;   // (+0.f, +0.f)

    for (int kq = 0; kq < 32; kq++) {
        const u64* wp = &g_W1p[mat][kq][0][0];
        ulonglong2 wa = *(const ulonglong2*)(wp + 4 * g);        // k01, cols 4g,4g+1
        ulonglong2 wb = *(const ulonglong2*)(wp + 4 * g + 2);    // k01, cols 4g+2,4g+3
        ulonglong2 wc = *(const ulonglong2*)(wp + 120 + 4 * g);  // k23, cols 4g,4g+1
        ulonglong2 wd = *(const ulonglong2*)(wp + 120 + 4 * g + 2);
#pragma unroll
        for (int j = 0; j < 8; j++) {
            ulonglong2 xj = sx[(l0 + j) * 32 + kq];  // .x = (x_k0,x_k1), .y = (x_k2,x_k3)
            FMA2(pacc[j][0], xj.x, wa.x); FMA2(pacc[j][0], xj.y, wc.x);
            FMA2(pacc[j][1], xj.x, wa.y); FMA2(pacc[j][1], xj.y, wc.y);
            FMA2(pacc[j][2], xj.x, wb.x); FMA2(pacc[j][2], xj.y, wd.x);
            FMA2(pacc[j][3], xj.x, wb.y); FMA2(pacc[j][3], xj.y, wd.y);
        }
    }
    if (lane < 30) {
#pragma unroll
        for (int j = 0; j < 8; j++) {
            float4 v = make_float4(sum2(pacc[j][0]), sum2(pacc[j][1]),
                                   sum2(pacc[j][2]), sum2(pacc[j][3]));
            *(float4*)(outp + (size_t)(nb + j) * F1 + lane * 4) = v;
        }
    }
}

// ---------------- layer1 aggregate: warp per dst node, 4-wide pipelined ----------------
__global__ void k_agg1(const float* __restrict__ att, const float* __restrict__ b1) {
    int dst = (blockIdx.x * blockDim.x + threadIdx.x) >> 5;
    int lane = threadIdx.x & 31;
    if (dst >= N_NODES) return;
    int g = lane < 30 ? lane : 0;

    float4 b = *((const float4*)(g_xr1 + (size_t)dst * F1) + g);
    float4 at = __ldg((const float4*)att + g);
    int s0 = g_rowstart[dst], s1 = g_rowstart[dst + 1];

    float4 acc = make_float4(0, 0, 0, 0);
    float den = 0.f;

#define EDGE1(A)                                                                  \
    {                                                                             \
        float p = lrelu(A.x + b.x) * at.x + lrelu(A.y + b.y) * at.y +             \
                  lrelu(A.z + b.z) * at.z + lrelu(A.w + b.w) * at.w;              \
        float p2 = __shfl_down_sync(FULL, p, 1);                                  \
        float ee = __expf(p + p2);                                                \
        float w = __shfl_sync(FULL, ee, lane & 30);                               \
        acc.x += w * A.x; acc.y += w * A.y; acc.z += w * A.z; acc.w += w * A.w;   \
        if ((lane & 1) == 0) den += ee;                                           \
    }

    int i = s0;
    for (; i + 3 < s1; i += 4) {
        int sa = g_csr_src[i], sb = g_csr_src[i + 1];
        int sc = g_csr_src[i + 2], sd = g_csr_src[i + 3];
        float4 a0 = __ldg((const float4*)(g_xl1 + (size_t)sa * F1) + g);
        float4 a1 = __ldg((const float4*)(g_xl1 + (size_t)sb * F1) + g);
        float4 a2 = __ldg((const float4*)(g_xl1 + (size_t)sc * F1) + g);
        float4 a3 = __ldg((const float4*)(g_xl1 + (size_t)sd * F1) + g);
        EDGE1(a0) EDGE1(a1) EDGE1(a2) EDGE1(a3)
    }
    for (; i < s1; i++) {
        int sa = g_csr_src[i];
        float4 a0 = __ldg((const float4*)(g_xl1 + (size_t)sa * F1) + g);
        EDGE1(a0)
    }
#undef EDGE1

    float d = __shfl_sync(FULL, den, lane & 30);
    if (lane < 30) {
        float4 bv = __ldg((const float4*)b1 + g);
        float inv = 1.f / d;
        float4 v;
        v.x = acc.x * inv + bv.x; v.y = acc.y * inv + bv.y;
        v.z = acc.z * inv + bv.z; v.w = acc.w * inv + bv.w;
        v.x = v.x > 0.f ? v.x : __expf(v.x) - 1.f;
        v.y = v.y > 0.f ? v.y : __expf(v.y) - 1.f;
        v.z = v.z > 0.f ? v.z : __expf(v.z) - 1.f;
        v.w = v.w > 0.f ? v.w : __expf(v.w) - 1.f;
        *(float4*)(g_h + (size_t)dst * F1 + lane * 4) = v;
    }
}

// ---------------- GEMM2: f32x2 packed FMA, smem x-tile, warp = 8 nodes, lane = col ----------------
__global__ void k_gemm2() {
    __shared__ ulonglong2 sx[32 * 30];          // 32 nodes x 120 floats = 15.4KB
    int tid = threadIdx.x;
    int nb0 = blockIdx.x * 32;

    const ulonglong2* h4 = (const ulonglong2*)g_h + (size_t)nb0 * 30;
    for (int i = tid; i < 32 * 30; i += 256)
        if (nb0 + i / 30 < N_NODES) sx[i] = h4[i];
    __syncthreads();

    int w = tid >> 5, lane = tid & 31;
    int mat = w & 1;
    int l0 = (w >> 1) * 8;
    int nb = nb0 + l0;
    if (nb >= N_NODES) return;

    float* outp = mat ? g_hr2 : g_hl2;

    u64 pacc[8];
#pragma unroll
    for (int j = 0; j < 8; j++) pacc[j] = 0ULL;

    for (int kq = 0; kq < 30; kq++) {
        u64 wa = g_W2p[mat][kq][0][lane];       // (w_k0, w_k1) for col=lane
        u64 wb = g_W2p[mat][kq][1][lane];       // (w_k2, w_k3)
#pragma unroll
        for (int j = 0; j < 8; j++) {
            ulonglong2 xj = sx[(l0 + j) * 30 + kq];
            FMA2(pacc[j], xj.x, wa);
            FMA2(pacc[j], xj.y, wb);
        }
    }
#pragma unroll
    for (int j = 0; j < 8; j++)
        outp[(size_t)(nb + j) * F2 + lane] = sum2(pacc[j]);
}

// ---------------- layer2 aggregate + bias + log_softmax: warp per dst, 4-wide ----------------
__global__ void k_agg2(const float* __restrict__ att2, const float* __restrict__ b2,
                       float* __restrict__ out) {
    int dst = (blockIdx.x * blockDim.x + threadIdx.x) >> 5;
    int lane = threadIdx.x & 31;
    if (dst >= N_NODES) return;

    float b = g_hr2[(size_t)dst * F2 + lane];
    float at = __ldg(&att2[lane]);
    int s0 = g_rowstart[dst], s1 = g_rowstart[dst + 1];

    float acc = 0.f, den = 0.f;

#define EDGE2(A)                                                    \
    {                                                               \
        float t = lrelu(A + b) * at;                                \
        _Pragma("unroll")                                           \
        for (int o = 16; o; o >>= 1) t += __shfl_xor_sync(FULL, t, o); \
        float w = __expf(t);                                        \
        den += w;                                                   \
        acc += w * A;                                               \
    }

    int i = s0;
    for (; i + 3 < s1; i += 4) {
        int sa = g_csr_src[i], sb = g_csr_src[i + 1];
        int sc = g_csr_src[i + 2], sd = g_csr_src[i + 3];
        float a0 = g_hl2[(size_t)sa * F2 + lane];
        float a1 = g_hl2[(size_t)sb * F2 + lane];
        float a2 = g_hl2[(size_t)sc * F2 + lane];
        float a3 = g_hl2[(size_t)sd * F2 + lane];
        EDGE2(a0) EDGE2(a1) EDGE2(a2) EDGE2(a3)
    }
    for (; i < s1; i++) {
        int sa = g_csr_src[i];
        float a0 = g_hl2[(size_t)sa * F2 + lane];
        EDGE2(a0)
    }
#undef EDGE2

    float v = acc / den + __ldg(&b2[lane]);
    float m = v;
#pragma unroll
    for (int o = 16; o; o >>= 1) m = fmaxf(m, __shfl_xor_sync(FULL, m, o));
    float ex = expf(v - m);
    float s = ex;
#pragma unroll
    for (int o = 16; o; o >>= 1) s += __shfl_xor_sync(FULL, s, o);
    float ls = v - m - logf(s);
    out[(size_t)dst * F2 + lane] = v;
    out[(size_t)N_NODES * F2 + (size_t)dst * F2 + lane] = ls;
}

// ---------------- launcher ----------------
extern "C" void kernel_launch(void* const* d_in, const int* in_sizes, int n_in,
                              void* d_out, int out_size) {
    const float* x    = (const float*)d_in[0];
    const int*   ei   = (const int*)d_in[1];     // dtype detected at runtime
    const float* W1l  = (const float*)d_in[2];
    const float* W1r  = (const float*)d_in[3];
    const float* att1 = (const float*)d_in[4];
    const float* b1   = (const float*)d_in[5];
    const float* W2l  = (const float*)d_in[6];
    const float* W2r  = (const float*)d_in[7];
    const float* att2 = (const float*)d_in[8];
    const float* b2   = (const float*)d_in[9];
    float* out = (float*)d_out;

    int gblocks = (N_NODES + 31) / 32;           // 1563

    k_init<<<(N_NODES + 255) / 256, 256>>>();
    k_detect<<<1, 256>>>(ei);
    k_packW<<<60, 256>>>(W1l, W1r, W2l, W2r);
    k_convert_count<<<(E_TOT + 255) / 256, 256>>>(ei);
    k_scan_a<<<NSCAN_BLK, 512>>>();
    k_scan_b<<<1, 128>>>();
    k_scan_c<<<NSCAN_BLK, 512>>>();
    k_fill<<<(E_TOT + 255) / 256, 256>>>();
    k_gemm1<<<gblocks, 256>>>(x);
    k_agg1<<<(N_NODES * 32 + 255) / 256, 256>>>(att1, b1);
    k_gemm2<<<gblocks, 256>>>();
    k_agg2<<<(N_NODES * 32 + 255) / 256, 256>>>(att2, b2, out);
}

// round 11
// speedup vs baseline: 1.1690x; 1.1690x over previous
#include <cuda_runtime.h>
#include <cstdint>
#include <float.h>

#define N_NODES 50000
#define E_RAW   800000
#define E_TOT   850000   // E_RAW + N_NODES self loops
#define H1      15
#define F1      120      // H1*8
#define DIN     128
#define F2      32

#define FULL 0xFFFFFFFFu
#define NSCAN_BLK 98     // ceil(N_NODES / 512)

// ---------------- scratch (device globals; no allocation allowed) ----------------
__device__ int      g_src[(size_t)E_TOT];
__device__ int      g_dst[(size_t)E_TOT];
__device__ int      g_cnt[(size_t)N_NODES];
__device__ int      g_cursor[(size_t)N_NODES];
__device__ int      g_rowstart[(size_t)N_NODES + 1];
__device__ int      g_csr_src[(size_t)E_TOT];
__device__ int      g_part[128];
__device__ int      g_partoff[128];
__device__ unsigned g_is64;                            // edge dtype flag
__device__ float    g_xl1[(size_t)N_NODES * F1];
__device__ float    g_xr1[(size_t)N_NODES * F1];
__device__ float    g_h[(size_t)N_NODES * F1];         // layer-1 activations (post ELU)
__device__ float    g_hl2[(size_t)N_NODES * F2];
__device__ float    g_hr2[(size_t)N_NODES * F2];

__device__ __forceinline__ float lrelu(float v) { return v > 0.f ? v : 0.2f * v; }

// ---------------- edge dtype detection (sampled; 1 block) ----------------
__global__ void k_detect(const int* __restrict__ ei_raw) {
    unsigned acc = 0;
    for (int i = threadIdx.x; i < 4096; i += 256)
        acc |= (unsigned)ei_raw[2 * i + 1];
#pragma unroll
    for (int o = 16; o; o >>= 1) acc |= __shfl_xor_sync(FULL, acc, o);
    if ((threadIdx.x & 31) == 0 && acc) atomicOr(&g_is64, 1u);
}

// ---------------- init ----------------
__global__ void k_init() {
    int i = blockIdx.x * blockDim.x + threadIdx.x;
    if (i == 0) g_is64 = 0u;
    if (i < N_NODES) { g_cnt[i] = 0; g_cursor[i] = 0; }
}

// ---------------- normalize edges (2 per thread, vectorized) + self loops + count ----------------
__global__ void k_convert_count(const int* __restrict__ ei_raw) {
    int t = blockIdx.x * blockDim.x + threadIdx.x;
    int e0 = t * 2;
    if (e0 >= E_TOT) return;

    int s0, d0, s1, d1;
    bool two = (e0 + 1 < E_TOT);

    if (e0 >= E_RAW) {                 // both are self loops
        s0 = d0 = e0 - E_RAW;
        s1 = d1 = e0 + 1 - E_RAW;
    } else if (e0 + 1 == E_RAW || !two) {   // boundary straddle: scalar path
        if (g_is64) {
            s0 = ei_raw[e0]; d0 = ei_raw[E_RAW + e0];
        } else {
            s0 = ei_raw[2 * e0]; d0 = ei_raw[2 * (E_RAW + e0)];
        }
        s1 = d1 = 0;
        if (two) { s1 = d1 = e0 + 1 - E_RAW; }
    } else if (g_is64) {               // int32 data
        int2 sv = *(const int2*)(ei_raw + e0);
        int2 dv = *(const int2*)(ei_raw + E_RAW + e0);
        s0 = sv.x; s1 = sv.y; d0 = dv.x; d1 = dv.y;
    } else {                           // int64 data: low words at 2*idx (e0 even -> aligned)
        int4 sv = *(const int4*)(ei_raw + 2 * e0);
        int4 dv = *(const int4*)(ei_raw + 2 * (E_RAW + e0));
        s0 = sv.x; s1 = sv.z; d0 = dv.x; d1 = dv.z;
    }

    *(int2*)(g_src + e0) = make_int2(s0, s1);
    *(int2*)(g_dst + e0) = make_int2(d0, d1);
    atomicAdd(&g_cnt[d0], 1);
    if (two) atomicAdd(&g_cnt[d1], 1);
}

// ---------------- parallel scan: pass A (block partial sums) ----------------
__global__ void k_scan_a() {
    int idx = blockIdx.x * 512 + threadIdx.x;
    int v = (idx < N_NODES) ? g_cnt[idx] : 0;
#pragma unroll
    for (int o = 16; o; o >>= 1) v += __shfl_down_sync(FULL, v, o);
    __shared__ int ws[16];
    if ((threadIdx.x & 31) == 0) ws[threadIdx.x >> 5] = v;
    __syncthreads();
    if (threadIdx.x < 16) {
        int s = ws[threadIdx.x];
#pragma unroll
        for (int o = 8; o; o >>= 1) s += __shfl_down_sync(0xFFFFu, s, o);
        if (threadIdx.x == 0) g_part[blockIdx.x] = s;
    }
}

// ---------------- parallel scan: pass B (scan 98 partials; 1 block x 128) ----------------
__global__ void k_scan_b() {
    int t = threadIdx.x;                       // 128 threads
    int v = (t < NSCAN_BLK) ? g_part[t] : 0;
    int lane = t & 31, wid = t >> 5;
    int inc = v;
#pragma unroll
    for (int o = 1; o < 32; o <<= 1) {
        int u = __shfl_up_sync(FULL, inc, o);
        if (lane >= o) inc += u;
    }
    __shared__ int ws[4];
    if (lane == 31) ws[wid] = inc;
    __syncthreads();
    int woff = 0;
    for (int i = 0; i < wid; i++) woff += ws[i];
    g_partoff[t] = inc - v + woff;             // exclusive
    if (t == 0) g_rowstart[N_NODES] = E_TOT;
}

// ---------------- parallel scan: pass C (block exclusive scan + offset) ----------------
__global__ void k_scan_c() {
    int idx = blockIdx.x * 512 + threadIdx.x;
    int v = (idx < N_NODES) ? g_cnt[idx] : 0;
    int lane = threadIdx.x & 31, wid = threadIdx.x >> 5;
    int inc = v;
#pragma unroll
    for (int o = 1; o < 32; o <<= 1) {
        int u = __shfl_up_sync(FULL, inc, o);
        if (lane >= o) inc += u;
    }
    __shared__ int ws[16];
    if (lane == 31) ws[wid] = inc;
    __syncthreads();
    if (threadIdx.x < 16) {
        int s = ws[threadIdx.x];
#pragma unroll
        for (int o = 1; o < 16; o <<= 1) {
            int u = __shfl_up_sync(0xFFFFu, s, o);
            if (threadIdx.x >= o) s += u;
        }
        ws[threadIdx.x] = s;
    }
    __syncthreads();
    int woff = wid ? ws[wid - 1] : 0;
    if (idx < N_NODES)
        g_rowstart[idx] = inc - v + woff + g_partoff[blockIdx.x];
}

// ---------------- fill CSR (src ids grouped by dst) ----------------
__global__ void k_fill() {
    int e = blockIdx.x * blockDim.x + threadIdx.x;
    if (e >= E_TOT) return;
    int dst = g_dst[e];
    int pos = g_rowstart[dst] + atomicAdd(&g_cursor[dst], 1);
    g_csr_src[pos] = g_src[e];
}

// ---------------- GEMM1: smem x-tile, warp = 8 nodes x ONE matrix ----------------
__global__ void k_gemm1(const float* __restrict__ x,
                        const float* __restrict__ Wl,
                        const float* __restrict__ Wr) {
    __shared__ float4 sx[32 * 32];              // 32 nodes x 128 floats = 16KB
    int tid = threadIdx.x;
    int nb0 = blockIdx.x * 32;

    const float4* x4 = (const float4*)x + (size_t)nb0 * 32;
    for (int i = tid; i < 32 * 32; i += 256)
        if (nb0 + (i >> 5) < N_NODES) sx[i] = x4[i];
    __syncthreads();

    int w = tid >> 5, lane = tid & 31;
    int mat = w & 1;
    int l0 = (w >> 1) * 8;
    int nb = nb0 + l0;
    if (nb >= N_NODES) return;                  // N % 8 == 0 -> whole group valid

    const float4* w4 = (const float4*)(mat ? Wr : Wl);   // row k -> k*30 + g
    float* outp = mat ? g_xr1 : g_xl1;
    int g = lane < 30 ? lane : 0;               // lanes 30,31 compute garbage, never store

    float4 acc[8];
#pragma unroll
    for (int j = 0; j < 8; j++) acc[j] = make_float4(0, 0, 0, 0);

    for (int kq = 0; kq < 32; kq++) {
        float4 w0 = __ldg(&w4[(size_t)(kq * 4 + 0) * 30 + g]);
        float4 w1 = __ldg(&w4[(size_t)(kq * 4 + 1) * 30 + g]);
        float4 w2 = __ldg(&w4[(size_t)(kq * 4 + 2) * 30 + g]);
        float4 w3 = __ldg(&w4[(size_t)(kq * 4 + 3) * 30 + g]);
#pragma unroll
        for (int j = 0; j < 8; j++) {
            float4 xj = sx[(l0 + j) * 32 + kq];   // broadcast LDS.128
            acc[j].x += xj.x * w0.x + xj.y * w1.x + xj.z * w2.x + xj.w * w3.x;
            acc[j].y += xj.x * w0.y + xj.y * w1.y + xj.z * w2.y + xj.w * w3.y;
            acc[j].z += xj.x * w0.z + xj.y * w1.z + xj.z * w2.z + xj.w * w3.z;
            acc[j].w += xj.x * w0.w + xj.y * w1.w + xj.z * w2.w + xj.w * w3.w;
        }
    }
    if (lane < 30) {
#pragma unroll
        for (int j = 0; j < 8; j++)
            *(float4*)(outp + (size_t)(nb + j) * F1 + lane * 4) = acc[j];
    }
}

// ---------------- layer1 aggregate: warp per dst node, 4-wide pipelined ----------------
__global__ void k_agg1(const float* __restrict__ att, const float* __restrict__ b1) {
    int dst = (blockIdx.x * blockDim.x + threadIdx.x) >> 5;
    int lane = threadIdx.x & 31;
    if (dst >= N_NODES) return;
    int g = lane < 30 ? lane : 0;

    float4 b = *((const float4*)(g_xr1 + (size_t)dst * F1) + g);
    float4 at = __ldg((const float4*)att + g);
    int s0 = g_rowstart[dst], s1 = g_rowstart[dst + 1];

    float4 acc = make_float4(0, 0, 0, 0);
    float den = 0.f;

#define EDGE1(A)                                                                  \
    {                                                                             \
        float p = lrelu(A.x + b.x) * at.x + lrelu(A.y + b.y) * at.y +             \
                  lrelu(A.z + b.z) * at.z + lrelu(A.w + b.w) * at.w;              \
        float p2 = __shfl_down_sync(FULL, p, 1);                                  \
        float ee = __expf(p + p2);                                                \
        float w = __shfl_sync(FULL, ee, lane & 30);                               \
        acc.x += w * A.x; acc.y += w * A.y; acc.z += w * A.z; acc.w += w * A.w;   \
        if ((lane & 1) == 0) den += ee;                                           \
    }

    int i = s0;
    for (; i + 3 < s1; i += 4) {
        int sa = g_csr_src[i], sb = g_csr_src[i + 1];
        int sc = g_csr_src[i + 2], sd = g_csr_src[i + 3];
        float4 a0 = __ldg((const float4*)(g_xl1 + (size_t)sa * F1) + g);
        float4 a1 = __ldg((const float4*)(g_xl1 + (size_t)sb * F1) + g);
        float4 a2 = __ldg((const float4*)(g_xl1 + (size_t)sc * F1) + g);
        float4 a3 = __ldg((const float4*)(g_xl1 + (size_t)sd * F1) + g);
        EDGE1(a0) EDGE1(a1) EDGE1(a2) EDGE1(a3)
    }
    for (; i < s1; i++) {
        int sa = g_csr_src[i];
        float4 a0 = __ldg((const float4*)(g_xl1 + (size_t)sa * F1) + g);
        EDGE1(a0)
    }
#undef EDGE1

    float d = __shfl_sync(FULL, den, lane & 30);
    if (lane < 30) {
        float4 bv = __ldg((const float4*)b1 + g);
        float inv = 1.f / d;
        float4 v;
        v.x = acc.x * inv + bv.x; v.y = acc.y * inv + bv.y;
        v.z = acc.z * inv + bv.z; v.w = acc.w * inv + bv.w;
        v.x = v.x > 0.f ? v.x : __expf(v.x) - 1.f;
        v.y = v.y > 0.f ? v.y : __expf(v.y) - 1.f;
        v.z = v.z > 0.f ? v.z : __expf(v.z) - 1.f;
        v.w = v.w > 0.f ? v.w : __expf(v.w) - 1.f;
        *(float4*)(g_h + (size_t)dst * F1 + lane * 4) = v;
    }
}

// ---------------- GEMM2: smem x-tile, warp = 8 nodes x ONE matrix, lane = col ----------------
__global__ void k_gemm2(const float* __restrict__ Wl, const float* __restrict__ Wr) {
    __shared__ float4 sx[32 * 30];              // 32 nodes x 120 floats = 15.4KB
    int tid = threadIdx.x;
    int nb0 = blockIdx.x * 32;

    const float4* h4 = (const float4*)g_h + (size_t)nb0 * 30;
    for (int i = tid; i < 32 * 30; i += 256)
        if (nb0 + i / 30 < N_NODES) sx[i] = h4[i];
    __syncthreads();

    int w = tid >> 5, lane = tid & 31;
    int mat = w & 1;
    int l0 = (w >> 1) * 8;
    int nb = nb0 + l0;
    if (nb >= N_NODES) return;

    const float* W = mat ? Wr : Wl;             // [F1, F2] row-major, lane = col
    float* outp = mat ? g_hr2 : g_hl2;

    float acc[8] = {0, 0, 0, 0, 0, 0, 0, 0};
    for (int kq = 0; kq < 30; kq++) {
        float w0 = __ldg(&W[(size_t)(kq * 4 + 0) * F2 + lane]);
        float w1 = __ldg(&W[(size_t)(kq * 4 + 1) * F2 + lane]);
        float w2 = __ldg(&W[(size_t)(kq * 4 + 2) * F2 + lane]);
        float w3 = __ldg(&W[(size_t)(kq * 4 + 3) * F2 + lane]);
#pragma unroll
        for (int j = 0; j < 8; j++) {
            float4 xj = sx[(l0 + j) * 30 + kq];
            acc[j] += xj.x * w0 + xj.y * w1 + xj.z * w2 + xj.w * w3;
        }
    }
#pragma unroll
    for (int j = 0; j < 8; j++)
        outp[(size_t)(nb + j) * F2 + lane] = acc[j];
}

// ---------------- layer2 aggregate + bias + log_softmax: warp per dst, 4-wide ----------------
__global__ void k_agg2(const float* __restrict__ att2, const float* __restrict__ b2,
                       float* __restrict__ out) {
    int dst = (blockIdx.x * blockDim.x + threadIdx.x) >> 5;
    int lane = threadIdx.x & 31;
    if (dst >= N_NODES) return;

    float b = g_hr2[(size_t)dst * F2 + lane];
    float at = __ldg(&att2[lane]);
    int s0 = g_rowstart[dst], s1 = g_rowstart[dst + 1];

    float acc = 0.f, den = 0.f;

#define EDGE2(A)                                                    \
    {                                                               \
        float t = lrelu(A + b) * at;                                \
        _Pragma("unroll")                                           \
        for (int o = 16; o; o >>= 1) t += __shfl_xor_sync(FULL, t, o); \
        float w = __expf(t);                                        \
        den += w;                                                   \
        acc += w * A;                                               \
    }

    int i = s0;
    for (; i + 3 < s1; i += 4) {
        int sa = g_csr_src[i], sb = g_csr_src[i + 1];
        int sc = g_csr_src[i + 2], sd = g_csr_src[i + 3];
        float a0 = g_hl2[(size_t)sa * F2 + lane];
        float a1 = g_hl2[(size_t)sb * F2 + lane];
        float a2 = g_hl2[(size_t)sc * F2 + lane];
        float a3 = g_hl2[(size_t)sd * F2 + lane];
        EDGE2(a0) EDGE2(a1) EDGE2(a2) EDGE2(a3)
    }
    for (; i < s1; i++) {
        int sa = g_csr_src[i];
        float a0 = g_hl2[(size_t)sa * F2 + lane];
        EDGE2(a0)
    }
#undef EDGE2

    float v = acc / den + __ldg(&b2[lane]);
    float m = v;
#pragma unroll
    for (int o = 16; o; o >>= 1) m = fmaxf(m, __shfl_xor_sync(FULL, m, o));
    float ex = expf(v - m);
    float s = ex;
#pragma unroll
    for (int o = 16; o; o >>= 1) s += __shfl_xor_sync(FULL, s, o);
    float ls = v - m - logf(s);
    out[(size_t)dst * F2 + lane] = v;
    out[(size_t)N_NODES * F2 + (size_t)dst * F2 + lane] = ls;
}

// ---------------- launcher (two-stream: CSR build overlaps GEMM1) ----------------
extern "C" void kernel_launch(void* const* d_in, const int* in_sizes, int n_in,
                              void* d_out, int out_size) {
    const float* x    = (const float*)d_in[0];
    const int*   ei   = (const int*)d_in[1];     // dtype detected at runtime
    const float* W1l  = (const float*)d_in[2];
    const float* W1r  = (const float*)d_in[3];
    const float* att1 = (const float*)d_in[4];
    const float* b1   = (const float*)d_in[5];
    const float* W2l  = (const float*)d_in[6];
    const float* W2r  = (const float*)d_in[7];
    const float* att2 = (const float*)d_in[8];
    const float* b2   = (const float*)d_in[9];
    float* out = (float*)d_out;

    static cudaStream_t s_side = nullptr;
    static cudaEvent_t  s_fork = nullptr, s_join = nullptr;
    if (!s_side) {
        cudaStreamCreateWithFlags(&s_side, cudaStreamNonBlocking);
        cudaEventCreateWithFlags(&s_fork, cudaEventDisableTiming);
        cudaEventCreateWithFlags(&s_join, cudaEventDisableTiming);
    }

    int gblocks = (N_NODES + 31) / 32;           // 1563

    // fork: CSR build on side stream, GEMM1 on main (default) stream
    cudaEventRecord(s_fork, 0);
    cudaStreamWaitEvent(s_side, s_fork, 0);

    k_init<<<(N_NODES + 255) / 256, 256, 0, s_side>>>();
    k_detect<<<1, 256, 0, s_side>>>(ei);
    k_convert_count<<<((E_TOT + 1) / 2 + 255) / 256, 256, 0, s_side>>>(ei);
    k_scan_a<<<NSCAN_BLK, 512, 0, s_side>>>();
    k_scan_b<<<1, 128, 0, s_side>>>();
    k_scan_c<<<NSCAN_BLK, 512, 0, s_side>>>();
    k_fill<<<(E_TOT + 255) / 256, 256, 0, s_side>>>();
    cudaEventRecord(s_join, s_side);

    k_gemm1<<<gblocks, 256>>>(x, W1l, W1r);

    // join: agg1 needs both GEMM1 output and the CSR
    cudaStreamWaitEvent(0, s_join, 0);
    k_agg1<<<(N_NODES * 32 + 255) / 256, 256>>>(att1, b1);
    k_gemm2<<<gblocks, 256>>>(W2l, W2r);
    k_agg2<<<(N_NODES * 32 + 255) / 256, 256>>>(att2, b2, out);
}

// round 12
// speedup vs baseline: 1.2118x; 1.0366x over previous
#include <cuda_runtime.h>
#include <cstdint>
#include <float.h>

#define N_NODES 50000
#define E_RAW   800000
#define E_TOT   850000   // E_RAW + N_NODES self loops
#define H1      15
#define F1      120      // H1*8
#define DIN     128
#define F2      32

#define FULL 0xFFFFFFFFu
#define NSCAN_BLK 98     // ceil(N_NODES / 512)

// ---------------- scratch (device globals; no allocation allowed) ----------------
__device__ int      g_src[(size_t)E_TOT];
__device__ int      g_dst[(size_t)E_TOT];
__device__ int      g_cnt[(size_t)N_NODES];
__device__ int      g_cursor[(size_t)N_NODES];
__device__ int      g_rowstart[(size_t)N_NODES + 1];
__device__ int      g_csr_src[(size_t)E_TOT];
__device__ int      g_part[128];
__device__ int      g_partoff[128];
__device__ unsigned g_is64;                            // edge dtype flag
__device__ float    g_xl1[(size_t)N_NODES * F1];
__device__ float    g_xr1[(size_t)N_NODES * F1];
__device__ float    g_hl2[(size_t)N_NODES * F2];
__device__ float    g_hr2[(size_t)N_NODES * F2];

__device__ __forceinline__ float lrelu(float v) { return v > 0.f ? v : 0.2f * v; }

// ---------------- edge dtype detection (sampled; 1 block) ----------------
__global__ void k_detect(const int* __restrict__ ei_raw) {
    unsigned acc = 0;
    for (int i = threadIdx.x; i < 4096; i += 256)
        acc |= (unsigned)ei_raw[2 * i + 1];
#pragma unroll
    for (int o = 16; o; o >>= 1) acc |= __shfl_xor_sync(FULL, acc, o);
    if ((threadIdx.x & 31) == 0 && acc) atomicOr(&g_is64, 1u);
}

// ---------------- init ----------------
__global__ void k_init() {
    int i = blockIdx.x * blockDim.x + threadIdx.x;
    if (i == 0) g_is64 = 0u;
    if (i < N_NODES) { g_cnt[i] = 0; g_cursor[i] = 0; }
}

// ---------------- normalize edges (2 per thread, vectorized) + self loops + count ----------------
__global__ void k_convert_count(const int* __restrict__ ei_raw) {
    int t = blockIdx.x * blockDim.x + threadIdx.x;
    int e0 = t * 2;
    if (e0 >= E_TOT) return;

    int s0, d0, s1, d1;
    bool two = (e0 + 1 < E_TOT);

    if (e0 >= E_RAW) {                 // both are self loops
        s0 = d0 = e0 - E_RAW;
        s1 = d1 = e0 + 1 - E_RAW;
    } else if (e0 + 1 == E_RAW || !two) {   // boundary straddle: scalar path
        if (g_is64) {
            s0 = ei_raw[e0]; d0 = ei_raw[E_RAW + e0];
        } else {
            s0 = ei_raw[2 * e0]; d0 = ei_raw[2 * (E_RAW + e0)];
        }
        s1 = d1 = 0;
        if (two) { s1 = d1 = e0 + 1 - E_RAW; }
    } else if (g_is64) {               // int32 data
        int2 sv = *(const int2*)(ei_raw + e0);
        int2 dv = *(const int2*)(ei_raw + E_RAW + e0);
        s0 = sv.x; s1 = sv.y; d0 = dv.x; d1 = dv.y;
    } else {                           // int64 data: low words at 2*idx (e0 even -> aligned)
        int4 sv = *(const int4*)(ei_raw + 2 * e0);
        int4 dv = *(const int4*)(ei_raw + 2 * (E_RAW + e0));
        s0 = sv.x; s1 = sv.z; d0 = dv.x; d1 = dv.z;
    }

    *(int2*)(g_src + e0) = make_int2(s0, s1);
    *(int2*)(g_dst + e0) = make_int2(d0, d1);
    atomicAdd(&g_cnt[d0], 1);
    if (two) atomicAdd(&g_cnt[d1], 1);
}

// ---------------- parallel scan: pass A (block partial sums) ----------------
__global__ void k_scan_a() {
    int idx = blockIdx.x * 512 + threadIdx.x;
    int v = (idx < N_NODES) ? g_cnt[idx] : 0;
#pragma unroll
    for (int o = 16; o; o >>= 1) v += __shfl_down_sync(FULL, v, o);
    __shared__ int ws[16];
    if ((threadIdx.x & 31) == 0) ws[threadIdx.x >> 5] = v;
    __syncthreads();
    if (threadIdx.x < 16) {
        int s = ws[threadIdx.x];
#pragma unroll
        for (int o = 8; o; o >>= 1) s += __shfl_down_sync(0xFFFFu, s, o);
        if (threadIdx.x == 0) g_part[blockIdx.x] = s;
    }
}

// ---------------- parallel scan: pass B (scan 98 partials; 1 block x 128) ----------------
__global__ void k_scan_b() {
    int t = threadIdx.x;                       // 128 threads
    int v = (t < NSCAN_BLK) ? g_part[t] : 0;
    int lane = t & 31, wid = t >> 5;
    int inc = v;
#pragma unroll
    for (int o = 1; o < 32; o <<= 1) {
        int u = __shfl_up_sync(FULL, inc, o);
        if (lane >= o) inc += u;
    }
    __shared__ int ws[4];
    if (lane == 31) ws[wid] = inc;
    __syncthreads();
    int woff = 0;
    for (int i = 0; i < wid; i++) woff += ws[i];
    g_partoff[t] = inc - v + woff;             // exclusive
    if (t == 0) g_rowstart[N_NODES] = E_TOT;
}

// ---------------- parallel scan: pass C (block exclusive scan + offset) ----------------
__global__ void k_scan_c() {
    int idx = blockIdx.x * 512 + threadIdx.x;
    int v = (idx < N_NODES) ? g_cnt[idx] : 0;
    int lane = threadIdx.x & 31, wid = threadIdx.x >> 5;
    int inc = v;
#pragma unroll
    for (int o = 1; o < 32; o <<= 1) {
        int u = __shfl_up_sync(FULL, inc, o);
        if (lane >= o) inc += u;
    }
    __shared__ int ws[16];
    if (lane == 31) ws[wid] = inc;
    __syncthreads();
    if (threadIdx.x < 16) {
        int s = ws[threadIdx.x];
#pragma unroll
        for (int o = 1; o < 16; o <<= 1) {
            int u = __shfl_up_sync(0xFFFFu, s, o);
            if (threadIdx.x >= o) s += u;
        }
        ws[threadIdx.x] = s;
    }
    __syncthreads();
    int woff = wid ? ws[wid - 1] : 0;
    if (idx < N_NODES)
        g_rowstart[idx] = inc - v + woff + g_partoff[blockIdx.x];
}

// ---------------- fill CSR (src ids grouped by dst) ----------------
__global__ void k_fill() {
    int e = blockIdx.x * blockDim.x + threadIdx.x;
    if (e >= E_TOT) return;
    int dst = g_dst[e];
    int pos = g_rowstart[dst] + atomicAdd(&g_cursor[dst], 1);
    g_csr_src[pos] = g_src[e];
}

// ---------------- GEMM1: smem x-tile, warp = 8 nodes x ONE matrix ----------------
__global__ void k_gemm1(const float* __restrict__ x,
                        const float* __restrict__ Wl,
                        const float* __restrict__ Wr) {
    __shared__ float4 sx[32 * 32];              // 32 nodes x 128 floats = 16KB
    int tid = threadIdx.x;
    int nb0 = blockIdx.x * 32;

    const float4* x4 = (const float4*)x + (size_t)nb0 * 32;
    for (int i = tid; i < 32 * 32; i += 256)
        if (nb0 + (i >> 5) < N_NODES) sx[i] = x4[i];
    __syncthreads();

    int w = tid >> 5, lane = tid & 31;
    int mat = w & 1;
    int l0 = (w >> 1) * 8;
    int nb = nb0 + l0;
    if (nb >= N_NODES) return;                  // N % 8 == 0 -> whole group valid

    const float4* w4 = (const float4*)(mat ? Wr : Wl);   // row k -> k*30 + g
    float* outp = mat ? g_xr1 : g_xl1;
    int g = lane < 30 ? lane : 0;               // lanes 30,31 compute garbage, never store

    float4 acc[8];
#pragma unroll
    for (int j = 0; j < 8; j++) acc[j] = make_float4(0, 0, 0, 0);

    for (int kq = 0; kq < 32; kq++) {
        float4 w0 = __ldg(&w4[(size_t)(kq * 4 + 0) * 30 + g]);
        float4 w1 = __ldg(&w4[(size_t)(kq * 4 + 1) * 30 + g]);
        float4 w2 = __ldg(&w4[(size_t)(kq * 4 + 2) * 30 + g]);
        float4 w3 = __ldg(&w4[(size_t)(kq * 4 + 3) * 30 + g]);
#pragma unroll
        for (int j = 0; j < 8; j++) {
            float4 xj = sx[(l0 + j) * 32 + kq];   // broadcast LDS.128
            acc[j].x += xj.x * w0.x + xj.y * w1.x + xj.z * w2.x + xj.w * w3.x;
            acc[j].y += xj.x * w0.y + xj.y * w1.y + xj.z * w2.y + xj.w * w3.y;
            acc[j].z += xj.x * w0.z + xj.y * w1.z + xj.z * w2.z + xj.w * w3.z;
            acc[j].w += xj.x * w0.w + xj.y * w1.w + xj.z * w2.w + xj.w * w3.w;
        }
    }
    if (lane < 30) {
#pragma unroll
        for (int j = 0; j < 8; j++)
            *(float4*)(outp + (size_t)(nb + j) * F1 + lane * 4) = acc[j];
    }
}

// ---------------- FUSED layer1 aggregate + GEMM2 (block = 32 dst nodes, 8 warps) ----------------
// Phase 1: warp w aggregates dst nodes nb0+4w..nb0+4w+3 (CSR, 4-wide pipelined),
//          applies /den + bias + ELU, writes h rows into the smem tile.
// Phase 2: warp = 8 nodes x ONE matrix (lane = output col) reads tile -> hl2/hr2.
__global__ void k_agg1gemm2(const float* __restrict__ att, const float* __restrict__ b1,
                            const float* __restrict__ Wl, const float* __restrict__ Wr) {
    __shared__ float4 sx[32 * 30];              // 32 nodes x 120 floats = 15.4KB
    int tid = threadIdx.x;
    int w = tid >> 5, lane = tid & 31;
    int nb0 = blockIdx.x * 32;
    int g = lane < 30 ? lane : 0;

    // ---- phase 1: aggregate 4 dst nodes per warp ----
    float4 at = __ldg((const float4*)att + g);
    float4 bv = __ldg((const float4*)b1 + g);

    for (int q = 0; q < 4; q++) {
        int l = w * 4 + q;                      // local node 0..31
        int dst = nb0 + l;
        if (dst >= N_NODES) break;

        float4 b = *((const float4*)(g_xr1 + (size_t)dst * F1) + g);
        int s0 = g_rowstart[dst], s1 = g_rowstart[dst + 1];

        float4 acc = make_float4(0, 0, 0, 0);
        float den = 0.f;

#define EDGE1(A)                                                                  \
    {                                                                             \
        float p = lrelu(A.x + b.x) * at.x + lrelu(A.y + b.y) * at.y +             \
                  lrelu(A.z + b.z) * at.z + lrelu(A.w + b.w) * at.w;              \
        float p2 = __shfl_down_sync(FULL, p, 1);                                  \
        float ee = __expf(p + p2);                                                \
        float ww = __shfl_sync(FULL, ee, lane & 30);                              \
        acc.x += ww * A.x; acc.y += ww * A.y; acc.z += ww * A.z; acc.w += ww * A.w; \
        if ((lane & 1) == 0) den += ee;                                           \
    }

        int i = s0;
        for (; i + 3 < s1; i += 4) {
            int sa = g_csr_src[i], sb = g_csr_src[i + 1];
            int sc = g_csr_src[i + 2], sd = g_csr_src[i + 3];
            float4 a0 = __ldg((const float4*)(g_xl1 + (size_t)sa * F1) + g);
            float4 a1 = __ldg((const float4*)(g_xl1 + (size_t)sb * F1) + g);
            float4 a2 = __ldg((const float4*)(g_xl1 + (size_t)sc * F1) + g);
            float4 a3 = __ldg((const float4*)(g_xl1 + (size_t)sd * F1) + g);
            EDGE1(a0) EDGE1(a1) EDGE1(a2) EDGE1(a3)
        }
        for (; i < s1; i++) {
            int sa = g_csr_src[i];
            float4 a0 = __ldg((const float4*)(g_xl1 + (size_t)sa * F1) + g);
            EDGE1(a0)
        }
#undef EDGE1

        float d = __shfl_sync(FULL, den, lane & 30);
        if (lane < 30) {
            float inv = 1.f / d;
            float4 v;
            v.x = acc.x * inv + bv.x; v.y = acc.y * inv + bv.y;
            v.z = acc.z * inv + bv.z; v.w = acc.w * inv + bv.w;
            v.x = v.x > 0.f ? v.x : __expf(v.x) - 1.f;
            v.y = v.y > 0.f ? v.y : __expf(v.y) - 1.f;
            v.z = v.z > 0.f ? v.z : __expf(v.z) - 1.f;
            v.w = v.w > 0.f ? v.w : __expf(v.w) - 1.f;
            sx[l * 30 + lane] = v;
        }
    }
    __syncthreads();

    // ---- phase 2: GEMM2 on the smem tile ----
    int mat = w & 1;
    int l0 = (w >> 1) * 8;
    int nb = nb0 + l0;
    if (nb >= N_NODES) return;

    const float* W = mat ? Wr : Wl;             // [F1, F2] row-major, lane = col
    float* outp = mat ? g_hr2 : g_hl2;

    float acc2[8] = {0, 0, 0, 0, 0, 0, 0, 0};
    for (int kq = 0; kq < 30; kq++) {
        float w0 = __ldg(&W[(size_t)(kq * 4 + 0) * F2 + lane]);
        float w1 = __ldg(&W[(size_t)(kq * 4 + 1) * F2 + lane]);
        float w2 = __ldg(&W[(size_t)(kq * 4 + 2) * F2 + lane]);
        float w3 = __ldg(&W[(size_t)(kq * 4 + 3) * F2 + lane]);
#pragma unroll
        for (int j = 0; j < 8; j++) {
            float4 xj = sx[(l0 + j) * 30 + kq];
            acc2[j] += xj.x * w0 + xj.y * w1 + xj.z * w2 + xj.w * w3;
        }
    }
#pragma unroll
    for (int j = 0; j < 8; j++)
        outp[(size_t)(nb + j) * F2 + lane] = acc2[j];
}

// ---------------- layer2 aggregate + bias + log_softmax: warp per dst, 4-wide ----------------
__global__ void k_agg2(const float* __restrict__ att2, const float* __restrict__ b2,
                       float* __restrict__ out) {
    int dst = (blockIdx.x * blockDim.x + threadIdx.x) >> 5;
    int lane = threadIdx.x & 31;
    if (dst >= N_NODES) return;

    float b = g_hr2[(size_t)dst * F2 + lane];
    float at = __ldg(&att2[lane]);
    int s0 = g_rowstart[dst], s1 = g_rowstart[dst + 1];

    float acc = 0.f, den = 0.f;

#define EDGE2(A)                                                    \
    {                                                               \
        float t = lrelu(A + b) * at;                                \
        _Pragma("unroll")                                           \
        for (int o = 16; o; o >>= 1) t += __shfl_xor_sync(FULL, t, o); \
        float w = __expf(t);                                        \
        den += w;                                                   \
        acc += w * A;                                               \
    }

    int i = s0;
    for (; i + 3 < s1; i += 4) {
        int sa = g_csr_src[i], sb = g_csr_src[i + 1];
        int sc = g_csr_src[i + 2], sd = g_csr_src[i + 3];
        float a0 = g_hl2[(size_t)sa * F2 + lane];
        float a1 = g_hl2[(size_t)sb * F2 + lane];
        float a2 = g_hl2[(size_t)sc * F2 + lane];
        float a3 = g_hl2[(size_t)sd * F2 + lane];
        EDGE2(a0) EDGE2(a1) EDGE2(a2) EDGE2(a3)
    }
    for (; i < s1; i++) {
        int sa = g_csr_src[i];
        float a0 = g_hl2[(size_t)sa * F2 + lane];
        EDGE2(a0)
    }
#undef EDGE2

    float v = acc / den + __ldg(&b2[lane]);
    float m = v;
#pragma unroll
    for (int o = 16; o; o >>= 1) m = fmaxf(m, __shfl_xor_sync(FULL, m, o));
    float ex = expf(v - m);
    float s = ex;
#pragma unroll
    for (int o = 16; o; o >>= 1) s += __shfl_xor_sync(FULL, s, o);
    float ls = v - m - logf(s);
    out[(size_t)dst * F2 + lane] = v;
    out[(size_t)N_NODES * F2 + (size_t)dst * F2 + lane] = ls;
}

// ---------------- launcher (two-stream: CSR build overlaps GEMM1) ----------------
extern "C" void kernel_launch(void* const* d_in, const int* in_sizes, int n_in,
                              void* d_out, int out_size) {
    const float* x    = (const float*)d_in[0];
    const int*   ei   = (const int*)d_in[1];     // dtype detected at runtime
    const float* W1l  = (const float*)d_in[2];
    const float* W1r  = (const float*)d_in[3];
    const float* att1 = (const float*)d_in[4];
    const float* b1   = (const float*)d_in[5];
    const float* W2l  = (const float*)d_in[6];
    const float* W2r  = (const float*)d_in[7];
    const float* att2 = (const float*)d_in[8];
    const float* b2   = (const float*)d_in[9];
    float* out = (float*)d_out;

    static cudaStream_t s_side = nullptr;
    static cudaEvent_t  s_fork = nullptr, s_join = nullptr;
    if (!s_side) {
        cudaStreamCreateWithFlags(&s_side, cudaStreamNonBlocking);
        cudaEventCreateWithFlags(&s_fork, cudaEventDisableTiming);
        cudaEventCreateWithFlags(&s_join, cudaEventDisableTiming);
    }

    int gblocks = (N_NODES + 31) / 32;           // 1563

    // fork: CSR build on side stream, GEMM1 on main (default) stream
    cudaEventRecord(s_fork, 0);
    cudaStreamWaitEvent(s_side, s_fork, 0);

    k_init<<<(N_NODES + 255) / 256, 256, 0, s_side>>>();
    k_detect<<<1, 256, 0, s_side>>>(ei);
    k_convert_count<<<((E_TOT + 1) / 2 + 255) / 256, 256, 0, s_side>>>(ei);
    k_scan_a<<<NSCAN_BLK, 512, 0, s_side>>>();
    k_scan_b<<<1, 128, 0, s_side>>>();
    k_scan_c<<<NSCAN_BLK, 512, 0, s_side>>>();
    k_fill<<<(E_TOT + 255) / 256, 256, 0, s_side>>>();
    cudaEventRecord(s_join, s_side);

    k_gemm1<<<gblocks, 256>>>(x, W1l, W1r);

    // join: fused agg1+gemm2 needs both GEMM1 output and the CSR
    cudaStreamWaitEvent(0, s_join, 0);
    k_agg1gemm2<<<gblocks, 256>>>(att1, b1, W2l, W2r);
    k_agg2<<<(N_NODES * 32 + 255) / 256, 256>>>(att2, b2, out);
}